// round 14
// baseline (speedup 1.0000x reference)
#include <cuda_runtime.h>
#include <cuda_fp16.h>
#include <cstdint>

// Problem constants
constexpr int Nn = 50000;
constexpr int Ee = 800000;
constexpr int Ff = 128;
constexpr int Hh = 256;
constexpr int Cc = 64;

constexpr int SCAN_B = 512;
constexpr int NBLK = (Nn + SCAN_B - 1) / SCAN_B;  // 98

// Scratch (fp16 activations)
__device__ __half g_hprime[(size_t)Nn * Ff];   // feature @ W_gcn (unscaled)
__device__ __half g_agg[(size_t)Nn * Ff];
__device__ __half g_hh[(size_t)Nn * Hh];
__device__ float g_deg[Nn];     // dinv
__device__ float g_acc[8];
__device__ int g_cnt[Nn];
__device__ int g_rowptr[Nn];    // block-local scan; post-fill = local row END
__device__ int g_bsum[128];
__device__ int g_esrc[Ee];

// ---------------------------------------------------------------------------
__global__ void init_k() {
    int i = blockIdx.x * blockDim.x + threadIdx.x;
    if (i < Nn) g_cnt[i] = 0;
    if (i < 8) g_acc[i] = 0.0f;
}
// 4 independent edges/thread for atomic MLP
__global__ void cnt_k(const int* __restrict__ adj) {
    constexpr int Q = Ee / 4;
    int t = blockIdx.x * blockDim.x + threadIdx.x;
    if (t >= Q) return;
    int d0 = adj[Ee + t];
    int d1 = adj[Ee + t + Q];
    int d2 = adj[Ee + t + 2 * Q];
    int d3 = adj[Ee + t + 3 * Q];
    atomicAdd(&g_cnt[d0], 1);
    atomicAdd(&g_cnt[d1], 1);
    atomicAdd(&g_cnt[d2], 1);
    atomicAdd(&g_cnt[d3], 1);
}
__global__ void scan1_k() {
    __shared__ int s[SCAN_B];
    int tid = threadIdx.x;
    int i = blockIdx.x * SCAN_B + tid;
    int v = (i < Nn) ? g_cnt[i] : 0;
    s[tid] = v;
    __syncthreads();
#pragma unroll
    for (int off = 1; off < SCAN_B; off <<= 1) {
        int t = (tid >= off) ? s[tid - off] : 0;
        __syncthreads();
        s[tid] += t;
        __syncthreads();
    }
    if (i < Nn) {
        g_rowptr[i] = s[tid] - v;
        g_deg[i] = rsqrtf((float)(v + 1));
    }
    if (tid == SCAN_B - 1) g_bsum[blockIdx.x] = s[tid];
}
__global__ void scan2_k() {
    __shared__ int ws[4];
    int tid = threadIdx.x;  // 128
    int v = (tid < NBLK) ? g_bsum[tid] : 0;
    int x = v;
#pragma unroll
    for (int o = 1; o < 32; o <<= 1) {
        int t = __shfl_up_sync(0xffffffffu, x, o);
        if ((tid & 31) >= o) x += t;
    }
    if ((tid & 31) == 31) ws[tid >> 5] = x;
    __syncthreads();
    if (tid == 0) {
        int run = 0;
#pragma unroll
        for (int i = 0; i < 4; i++) { int t = ws[i]; ws[i] = run; run += t; }
    }
    __syncthreads();
    if (tid < NBLK) g_bsum[tid] = x - v + ws[tid >> 5];
}
// fill: rowptr doubles as cursor; 4 independent edges/thread
__global__ void fill_k(const int* __restrict__ adj) {
    constexpr int Q = Ee / 4;
    int t = blockIdx.x * blockDim.x + threadIdx.x;
    if (t >= Q) return;
    int s0 = adj[t],         d0 = adj[Ee + t];
    int s1 = adj[t + Q],     d1 = adj[Ee + t + Q];
    int s2 = adj[t + 2 * Q], d2 = adj[Ee + t + 2 * Q];
    int s3 = adj[t + 3 * Q], d3 = adj[Ee + t + 3 * Q];
    int p0 = atomicAdd(&g_rowptr[d0], 1);
    int p1 = atomicAdd(&g_rowptr[d1], 1);
    int p2 = atomicAdd(&g_rowptr[d2], 1);
    int p3 = atomicAdd(&g_rowptr[d3], 1);
    g_esrc[p0 + g_bsum[d0 >> 9]] = s0;
    g_esrc[p1 + g_bsum[d1 >> 9]] = s1;
    g_esrc[p2 + g_bsum[d2 >> 9]] = s2;
    g_esrc[p3 + g_bsum[d3 >> 9]] = s3;
}

// ---------------------------------------------------------------------------
__device__ __forceinline__ uint32_t smem_u32(const void* p) {
    uint32_t a;
    asm("{ .reg .u64 t; cvta.to.shared.u64 t, %1; cvt.u32.u64 %0, t; }"
        : "=r"(a) : "l"(p));
    return a;
}
__device__ __forceinline__ void ldsm_x4(uint32_t* r, uint32_t addr) {
    asm volatile("ldmatrix.sync.aligned.m8n8.x4.shared.b16 {%0,%1,%2,%3}, [%4];"
                 : "=r"(r[0]), "=r"(r[1]), "=r"(r[2]), "=r"(r[3]) : "r"(addr));
}
__device__ __forceinline__ void ldsm_x2t(uint32_t* r, uint32_t addr) {
    asm volatile("ldmatrix.sync.aligned.m8n8.x2.trans.shared.b16 {%0,%1}, [%2];"
                 : "=r"(r[0]), "=r"(r[1]) : "r"(addr));
}
__device__ __forceinline__ void mma_f16(float* d, const uint32_t* a, const uint32_t* b) {
    asm volatile(
        "mma.sync.aligned.m16n8k16.row.col.f32.f16.f16.f32 "
        "{%0,%1,%2,%3}, {%4,%5,%6,%7}, {%8,%9}, {%0,%1,%2,%3};"
        : "+f"(d[0]), "+f"(d[1]), "+f"(d[2]), "+f"(d[3])
        : "r"(a[0]), "r"(a[1]), "r"(a[2]), "r"(a[3]), "r"(b[0]), "r"(b[1]));
}
__device__ __forceinline__ uint32_t pack_h2(__half a, __half b) {
    __half2 h = __halves2half2(a, b);
    return *(uint32_t*)&h;
}
__device__ __forceinline__ float4 h4_to_f4(uint2 u) {
    float2 fa = __half22float2(*(__half2*)&u.x);
    float2 fb = __half22float2(*(__half2*)&u.y);
    return make_float4(fa.x, fa.y, fb.x, fb.y);
}
__device__ __forceinline__ uint2 f4_to_h4(float4 v) {
    __half2 a = __floats2half2_rn(v.x, v.y);
    __half2 b = __floats2half2_rn(v.z, v.w);
    uint2 u;
    u.x = *(uint32_t*)&a;
    u.y = *(uint32_t*)&b;
    return u;
}

// ---------------------------------------------------------------------------
// fp16 2-term HMMA GEMM: C = A@B via Ah*(Bh+Bl); A single fp16, B split hi/lo.
// BM=128, BN=64, BK=32, 256 threads, 8 warps (4m x 2n), warp tile 32x32.
// AHALF: 0 -> A fp32 ; 1 -> A fp16
// AXF:   1 -> A'[r][k] = dinv[r]*A[r][k] + abias[k]
// EPI:   1 -> relu(v+bias) -> half C0
//        2 -> plain v -> half C0
//        3 -> v+bias -> fp32 C0 replicated to 3 slices + FUSED LOSS
template <int K, int AHALF, int AXF, int EPI>
__global__ void __launch_bounds__(256)
mmagemm(const void* __restrict__ Ap, const float* __restrict__ B,
        const float* __restrict__ abias, const float* __restrict__ bias,
        void* __restrict__ C0p, int M, int Ncol,
        const int* __restrict__ label, const int* __restrict__ mk0,
        const int* __restrict__ mk1, const int* __restrict__ mk2) {
    constexpr int ASTR = 40;
    constexpr int BSTR = 72;
    __shared__ __align__(16) __half Ash[128 * ASTR];
    __shared__ __align__(16) __half Bsh[32 * BSTR];
    __shared__ __align__(16) __half Bsl[32 * BSTR];

    const int tid = threadIdx.x;
    const int wid = tid >> 5;
    const int lane = tid & 31;
    const int wm = wid & 3;
    const int wn = wid >> 2;
    const int m0 = blockIdx.x * 128;
    const int n0 = blockIdx.y * 64;

    const uint32_t uAs = smem_u32(Ash);
    const uint32_t uBh = smem_u32(Bsh);
    const uint32_t uBl = smem_u32(Bsl);

    const int l15 = lane & 15;
    const int lh = lane >> 4;
    uint32_t aOff[2];
#pragma unroll
    for (int mi = 0; mi < 2; mi++)
        aOff[mi] = uAs + (uint32_t)((wm * 32 + mi * 16 + l15) * (ASTR * 2) + lh * 16);
    const uint32_t bOff = (uint32_t)(l15 * (BSTR * 2) + wn * 64);

    float acc[2][4][4];
#pragma unroll
    for (int mi = 0; mi < 2; mi++)
#pragma unroll
        for (int ni = 0; ni < 4; ni++)
#pragma unroll
            for (int j = 0; j < 4; j++) acc[mi][ni][j] = 0.0f;

    constexpr int NC = K / 32;
#pragma unroll 1
    for (int c = 0; c < NC; c++) {
        const int k0 = c * 32;
        if (c > 0) __syncthreads();
        if (AHALF == 0) {
            const float* A = (const float*)Ap;
#pragma unroll
            for (int it = 0; it < 4; it++) {
                int idx = it * 256 + tid;
                int r = idx >> 3, q = idx & 7;
                int gr = m0 + r;
                float4 v = make_float4(0.f, 0.f, 0.f, 0.f);
                if (gr < M) {
                    v = *(const float4*)(A + (size_t)gr * K + k0 + q * 4);
                    if (AXF) {
                        float sc = g_deg[gr];
                        float4 bb = *(const float4*)(abias + k0 + q * 4);
                        v.x = sc * v.x + bb.x; v.y = sc * v.y + bb.y;
                        v.z = sc * v.z + bb.z; v.w = sc * v.w + bb.w;
                    }
                }
                uint2 u;
                u.x = pack_h2(__float2half_rn(v.x), __float2half_rn(v.y));
                u.y = pack_h2(__float2half_rn(v.z), __float2half_rn(v.w));
                *(uint2*)&Ash[r * ASTR + q * 4] = u;
            }
        } else {
            const __half* A = (const __half*)Ap;
#pragma unroll
            for (int it = 0; it < 2; it++) {
                int idx = it * 256 + tid;
                int r = idx >> 2, q = idx & 3;
                int gr = m0 + r;
                uint4 u = make_uint4(0, 0, 0, 0);
                if (gr < M) {
                    u = *(const uint4*)(A + (size_t)gr * K + k0 + q * 8);
                    if (AXF) {
                        float sc = g_deg[gr];
                        float4 b0 = *(const float4*)(abias + k0 + q * 8);
                        float4 b1 = *(const float4*)(abias + k0 + q * 8 + 4);
                        float4 f0 = h4_to_f4(make_uint2(u.x, u.y));
                        float4 f1 = h4_to_f4(make_uint2(u.z, u.w));
                        f0.x = sc * f0.x + b0.x; f0.y = sc * f0.y + b0.y;
                        f0.z = sc * f0.z + b0.z; f0.w = sc * f0.w + b0.w;
                        f1.x = sc * f1.x + b1.x; f1.y = sc * f1.y + b1.y;
                        f1.z = sc * f1.z + b1.z; f1.w = sc * f1.w + b1.w;
                        uint2 p0 = f4_to_h4(f0), p1 = f4_to_h4(f1);
                        u = make_uint4(p0.x, p0.y, p1.x, p1.y);
                    }
                }
                *(uint4*)&Ash[r * ASTR + q * 8] = u;
            }
        }
#pragma unroll
        for (int it = 0; it < 2; it++) {
            int idx = it * 256 + tid;
            int kk = idx >> 4, n4 = (idx & 15) * 4;
            float4 v = *(const float4*)(B + (size_t)(k0 + kk) * Ncol + n0 + n4);
            __half hx = __float2half_rn(v.x), hy = __float2half_rn(v.y);
            __half hz = __float2half_rn(v.z), hw = __float2half_rn(v.w);
            __half lx = __float2half_rn(v.x - __half2float(hx));
            __half ly = __float2half_rn(v.y - __half2float(hy));
            __half lz = __float2half_rn(v.z - __half2float(hz));
            __half lw = __float2half_rn(v.w - __half2float(hw));
            uint2 uh, ul;
            uh.x = pack_h2(hx, hy); uh.y = pack_h2(hz, hw);
            ul.x = pack_h2(lx, ly); ul.y = pack_h2(lz, lw);
            *(uint2*)&Bsh[kk * BSTR + n4] = uh;
            *(uint2*)&Bsl[kk * BSTR + n4] = ul;
        }
        __syncthreads();

#pragma unroll
        for (int ks = 0; ks < 2; ks++) {
            uint32_t ah[2][4], bh[4][2], bl[4][2];
#pragma unroll
            for (int mi = 0; mi < 2; mi++)
                ldsm_x4(ah[mi], aOff[mi] + ks * 32);
#pragma unroll
            for (int ni = 0; ni < 4; ni++) {
                uint32_t bo = bOff + ks * 16 * (BSTR * 2) + ni * 16;
                ldsm_x2t(bh[ni], uBh + bo);
                ldsm_x2t(bl[ni], uBl + bo);
            }
#pragma unroll
            for (int mi = 0; mi < 2; mi++)
#pragma unroll
                for (int ni = 0; ni < 4; ni++) {
                    mma_f16(acc[mi][ni], ah[mi], bh[ni]);
                    mma_f16(acc[mi][ni], ah[mi], bl[ni]);
                }
        }
    }

    const int g = lane >> 2;
    const int tig = lane & 3;

    if (EPI == 1 || EPI == 2) {
#pragma unroll
        for (int mi = 0; mi < 2; mi++) {
            int row0 = m0 + wm * 32 + mi * 16 + g;
            int row1 = row0 + 8;
#pragma unroll
            for (int ni = 0; ni < 4; ni++) {
                int col = n0 + wn * 32 + ni * 8 + tig * 2;
                float v0 = acc[mi][ni][0], v1 = acc[mi][ni][1];
                float v2 = acc[mi][ni][2], v3 = acc[mi][ni][3];
                if (EPI == 1) {
                    float2 b = *(const float2*)(bias + col);
                    v0 = fmaxf(v0 + b.x, 0.f); v1 = fmaxf(v1 + b.y, 0.f);
                    v2 = fmaxf(v2 + b.x, 0.f); v3 = fmaxf(v3 + b.y, 0.f);
                }
                __half* C = (__half*)C0p;
                if (row0 < M)
                    *(__half2*)(C + (size_t)row0 * Ncol + col) = __floats2half2_rn(v0, v1);
                if (row1 < M)
                    *(__half2*)(C + (size_t)row1 * Ncol + col) = __floats2half2_rn(v2, v3);
            }
        }
        return;
    }

    // ================= EPI == 3: logits + replication + fused loss ==========
    __shared__ float sred[2][128];   // [wn][row_local]
    __shared__ float sacc[6];
    if (tid < 6) sacc[tid] = 0.0f;

    // add bias in place; store to 3 slices
#pragma unroll
    for (int mi = 0; mi < 2; mi++) {
        int row0 = m0 + wm * 32 + mi * 16 + g;
        int row1 = row0 + 8;
#pragma unroll
        for (int ni = 0; ni < 4; ni++) {
            int col = n0 + wn * 32 + ni * 8 + tig * 2;
            float2 b = *(const float2*)(bias + col);
            acc[mi][ni][0] += b.x; acc[mi][ni][1] += b.y;
            acc[mi][ni][2] += b.x; acc[mi][ni][3] += b.y;
            float* C = (float*)C0p;
            if (row0 < M) {
                float* p = C + (size_t)row0 * Ncol + col;
                float2 t = make_float2(acc[mi][ni][0], acc[mi][ni][1]);
                *(float2*)p = t;
                *(float2*)(p + (size_t)Nn * Cc) = t;
                *(float2*)(p + (size_t)2 * Nn * Cc) = t;
            }
            if (row1 < M) {
                float* p = C + (size_t)row1 * Ncol + col;
                float2 t = make_float2(acc[mi][ni][2], acc[mi][ni][3]);
                *(float2*)p = t;
                *(float2*)(p + (size_t)Nn * Cc) = t;
                *(float2*)(p + (size_t)2 * Nn * Cc) = t;
            }
        }
    }

    // Phase A: per-row max (within warp cols, reduce over tig lanes)
    float pmax[2][2];
#pragma unroll
    for (int mi = 0; mi < 2; mi++) {
        float h0 = acc[mi][0][0], h1 = acc[mi][0][2];
        h0 = fmaxf(h0, acc[mi][0][1]); h1 = fmaxf(h1, acc[mi][0][3]);
#pragma unroll
        for (int ni = 1; ni < 4; ni++) {
            h0 = fmaxf(h0, fmaxf(acc[mi][ni][0], acc[mi][ni][1]));
            h1 = fmaxf(h1, fmaxf(acc[mi][ni][2], acc[mi][ni][3]));
        }
#pragma unroll
        for (int o = 1; o < 4; o <<= 1) {
            h0 = fmaxf(h0, __shfl_xor_sync(0xffffffffu, h0, o));
            h1 = fmaxf(h1, __shfl_xor_sync(0xffffffffu, h1, o));
        }
        pmax[mi][0] = h0; pmax[mi][1] = h1;
    }
    __syncthreads();   // sacc init + any smem reuse ordering
    if (tig == 0) {
#pragma unroll
        for (int mi = 0; mi < 2; mi++) {
            sred[wn][wm * 32 + mi * 16 + g] = pmax[mi][0];
            sred[wn][wm * 32 + mi * 16 + g + 8] = pmax[mi][1];
        }
    }
    __syncthreads();
    float rmax[2][2];
#pragma unroll
    for (int mi = 0; mi < 2; mi++) {
        int rl0 = wm * 32 + mi * 16 + g;
        rmax[mi][0] = fmaxf(sred[0][rl0], sred[1][rl0]);
        rmax[mi][1] = fmaxf(sred[0][rl0 + 8], sred[1][rl0 + 8]);
    }
    __syncthreads();   // all reads of sred done before overwrite

    // Phase B: sum of exp
    float psum[2][2];
#pragma unroll
    for (int mi = 0; mi < 2; mi++) {
        float s0 = 0.f, s1 = 0.f;
#pragma unroll
        for (int ni = 0; ni < 4; ni++) {
            s0 += expf(acc[mi][ni][0] - rmax[mi][0]) + expf(acc[mi][ni][1] - rmax[mi][0]);
            s1 += expf(acc[mi][ni][2] - rmax[mi][1]) + expf(acc[mi][ni][3] - rmax[mi][1]);
        }
#pragma unroll
        for (int o = 1; o < 4; o <<= 1) {
            s0 += __shfl_xor_sync(0xffffffffu, s0, o);
            s1 += __shfl_xor_sync(0xffffffffu, s1, o);
        }
        psum[mi][0] = s0; psum[mi][1] = s1;
    }
    if (tig == 0) {
#pragma unroll
        for (int mi = 0; mi < 2; mi++) {
            sred[wn][wm * 32 + mi * 16 + g] = psum[mi][0];
            sred[wn][wm * 32 + mi * 16 + g + 8] = psum[mi][1];
        }
    }
    __syncthreads();

    // Phase C: loss for label-matching element
#pragma unroll
    for (int mi = 0; mi < 2; mi++) {
#pragma unroll
        for (int hf = 0; hf < 2; hf++) {
            int rl = wm * 32 + mi * 16 + g + hf * 8;
            int row = m0 + rl;
            if (row >= M) continue;
            int lb = label[row];
            int cbase = wn * 32 + tig * 2;     // + ni*8 + parity
            int rel = lb - cbase;
            // rel must equal ni*8 + parity with parity in {0,1}
            if (rel >= 0 && rel < 32 && (rel & 7) <= 1) {
                int ni = rel >> 3;
                int par = rel & 1;
                float v = acc[mi][ni][hf * 2 + par];
                float lse = rmax[mi][hf] + logf(sred[0][rl] + sred[1][rl]);
                float loss = lse - v;
                float t0 = (mk0[row] == 1) ? 1.0f : 0.0f;
                float t1 = (mk1[row] == 1) ? 1.0f : 0.0f;
                float t2 = (mk2[row] == 1) ? 1.0f : 0.0f;
                atomicAdd(&sacc[0], loss * t0);
                atomicAdd(&sacc[1], loss * t1);
                atomicAdd(&sacc[2], loss * t2);
                atomicAdd(&sacc[3], t0);
                atomicAdd(&sacc[4], t1);
                atomicAdd(&sacc[5], t2);
            }
        }
    }
    __syncthreads();
    if (tid < 6) atomicAdd(&g_acc[tid], sacc[tid]);
}

// ---------------------------------------------------------------------------
// CSR gather with per-source dinv scaling:
// agg[d] = dinv[d]*hprime[d] + sum_s dinv[s]*hprime[s]
__global__ void gather_k() {
    int d = blockIdx.x * 8 + (threadIdx.x >> 5);
    int lane = threadIdx.x & 31;
    if (d >= Nn) return;
    const uint2* hp = (const uint2*)g_hprime;
    float sd = g_deg[d];
    float4 self = h4_to_f4(hp[(size_t)d * 32 + lane]);
    float4 a0, a1, a2, a3;
    a0.x = sd * self.x; a0.y = sd * self.y; a0.z = sd * self.z; a0.w = sd * self.w;
    a1 = make_float4(0.f, 0.f, 0.f, 0.f);
    a2 = make_float4(0.f, 0.f, 0.f, 0.f);
    a3 = make_float4(0.f, 0.f, 0.f, 0.f);
    int base = g_bsum[d >> 9];
    int end = g_rowptr[d] + base;
    int beg = end - g_cnt[d];
    int e = beg;
    for (; e + 3 < end; e += 4) {
        int s0 = g_esrc[e], s1 = g_esrc[e + 1], s2 = g_esrc[e + 2], s3 = g_esrc[e + 3];
        float c0 = g_deg[s0], c1 = g_deg[s1], c2 = g_deg[s2], c3 = g_deg[s3];
        float4 v0 = h4_to_f4(hp[(size_t)s0 * 32 + lane]);
        float4 v1 = h4_to_f4(hp[(size_t)s1 * 32 + lane]);
        float4 v2 = h4_to_f4(hp[(size_t)s2 * 32 + lane]);
        float4 v3 = h4_to_f4(hp[(size_t)s3 * 32 + lane]);
        a0.x += c0 * v0.x; a0.y += c0 * v0.y; a0.z += c0 * v0.z; a0.w += c0 * v0.w;
        a1.x += c1 * v1.x; a1.y += c1 * v1.y; a1.z += c1 * v1.z; a1.w += c1 * v1.w;
        a2.x += c2 * v2.x; a2.y += c2 * v2.y; a2.z += c2 * v2.z; a2.w += c2 * v2.w;
        a3.x += c3 * v3.x; a3.y += c3 * v3.y; a3.z += c3 * v3.z; a3.w += c3 * v3.w;
    }
    for (; e < end; e++) {
        int s0 = g_esrc[e];
        float c0 = g_deg[s0];
        float4 v0 = h4_to_f4(hp[(size_t)s0 * 32 + lane]);
        a0.x += c0 * v0.x; a0.y += c0 * v0.y; a0.z += c0 * v0.z; a0.w += c0 * v0.w;
    }
    a0.x += a1.x + a2.x + a3.x;
    a0.y += a1.y + a2.y + a3.y;
    a0.z += a1.z + a2.z + a3.z;
    a0.w += a1.w + a2.w + a3.w;
    ((uint2*)g_agg)[(size_t)d * 32 + lane] = f4_to_h4(a0);
}

// ---------------------------------------------------------------------------
__global__ void finalize_k(float* __restrict__ out) {
    int k = threadIdx.x;
    if (k < 3) out[(size_t)3 * Nn * Cc + k] = g_acc[k] / g_acc[3 + k];
}

// ---------------------------------------------------------------------------
extern "C" void kernel_launch(void* const* d_in, const int* in_sizes, int n_in,
                              void* d_out, int out_size) {
    const float* feature = (const float*)d_in[0];
    const int* adj       = (const int*)d_in[1];
    const int* label     = (const int*)d_in[2];
    const int* tmask     = (const int*)d_in[3];
    const int* dmask     = (const int*)d_in[4];
    const int* temask    = (const int*)d_in[5];
    const float* W_gcn   = (const float*)d_in[6];
    const float* b_gcn   = (const float*)d_in[7];
    const float* W_ff    = (const float*)d_in[8];
    const float* b_ff    = (const float*)d_in[9];
    const float* W_pred  = (const float*)d_in[10];
    const float* b_pred  = (const float*)d_in[11];
    float* out = (float*)d_out;

    void* d_hprime; cudaGetSymbolAddress(&d_hprime, g_hprime);
    void* d_agg;    cudaGetSymbolAddress(&d_agg, g_agg);
    void* d_hh;     cudaGetSymbolAddress(&d_hh, g_hh);

    const int MB = (Nn + 127) / 128;  // 391

    // side stream + events (created once on the eager correctness call)
    static cudaStream_t s2 = nullptr;
    static cudaEvent_t evFork = nullptr, evJoin = nullptr;
    if (!s2) {
        cudaStreamCreateWithFlags(&s2, cudaStreamNonBlocking);
        cudaEventCreateWithFlags(&evFork, cudaEventDisableTiming);
        cudaEventCreateWithFlags(&evJoin, cudaEventDisableTiming);
    }

    // fork: CSR build + dinv on s2, gemm1 on main stream
    cudaEventRecord(evFork, 0);
    cudaStreamWaitEvent(s2, evFork, 0);

    init_k<<<(Nn + 255) / 256, 256, 0, s2>>>();
    cnt_k<<<(Ee / 4 + 255) / 256, 256, 0, s2>>>(adj);
    scan1_k<<<NBLK, SCAN_B, 0, s2>>>();
    scan2_k<<<1, 128, 0, s2>>>();
    fill_k<<<(Ee / 4 + 255) / 256, 256, 0, s2>>>(adj);

    // gemm1: hprime = feature @ W_gcn (unscaled; dinv applied in gather)
    {
        dim3 grid(MB, Ff / 64);
        mmagemm<128, 0, 0, 2><<<grid, 256>>>(feature, W_gcn, nullptr, nullptr,
                                             d_hprime, Nn, Ff,
                                             nullptr, nullptr, nullptr, nullptr);
    }

    // join
    cudaEventRecord(evJoin, s2);
    cudaStreamWaitEvent(0, evJoin, 0);

    gather_k<<<(Nn + 7) / 8, 256>>>();

    {
        dim3 grid(MB, Hh / 64);
        mmagemm<128, 1, 1, 1><<<grid, 256>>>(d_agg, W_ff, b_gcn, b_ff,
                                             d_hh, Nn, Hh,
                                             nullptr, nullptr, nullptr, nullptr);
    }
    // gemm3: logits -> 3 slices + fused loss accumulation
    {
        dim3 grid(MB, Cc / 64);  // grid.y == 1
        mmagemm<256, 1, 0, 3><<<grid, 256>>>(d_hh, W_pred, nullptr, b_pred,
                                             out, Nn, Cc,
                                             label, tmask, dmask, temask);
    }

    finalize_k<<<1, 32>>>(out);
}